// round 6
// baseline (speedup 1.0000x reference)
#include <cuda_runtime.h>
#include <cstdint>

#define CH   256
#define IMG  128
#define HW   (IMG*IMG)
#define BATCH 4
#define HEADS 4
#define D    64
#define BLK  8
#define HALO 3
#define WIN  14
#define NB   16
#define NPOS 64
#define NWIN 196

typedef unsigned long long ull;

__device__ __forceinline__ ull pack2(float lo, float hi) {
    ull r; asm("mov.b64 %0, {%1,%2};" : "=l"(r) : "f"(lo), "f"(hi)); return r;
}
__device__ __forceinline__ ull pack2b(float v) { return pack2(v, v); }
__device__ __forceinline__ void fma2(ull& d, ull a, ull b) {
    asm("fma.rn.f32x2 %0, %1, %2, %0;" : "+l"(d) : "l"(a), "l"(b));
}
__device__ __forceinline__ void unpack2(ull v, float& lo, float& hi) {
    asm("mov.b64 {%0,%1}, %2;" : "=f"(lo), "=f"(hi) : "l"(v));
}
__device__ __forceinline__ float tf32r(float x) {
    uint32_t r; asm("cvt.rna.tf32.f32 %0, %1;" : "=r"(r) : "f"(x));
    return __uint_as_float(r);
}
__device__ __forceinline__ void mma8(float* d, uint32_t a0, uint32_t a1,
                                     uint32_t a2, uint32_t a3,
                                     uint32_t b0, uint32_t b1) {
    asm("mma.sync.aligned.m16n8k8.row.col.f32.tf32.tf32.f32 "
        "{%0,%1,%2,%3},{%4,%5,%6,%7},{%8,%9},{%0,%1,%2,%3};"
        : "+f"(d[0]), "+f"(d[1]), "+f"(d[2]), "+f"(d[3])
        : "r"(a0), "r"(a1), "r"(a2), "r"(a3), "r"(b0), "r"(b1));
}

// Scratch; g_k/g_v padded 16 floats front+back for aligned halo float4 loads.
__device__ float g_naux[(long)BATCH*CH*HW];
__device__ float g_q   [(long)BATCH*CH*HW];
__device__ float g_k   [(long)BATCH*CH*HW + 32];
__device__ float g_v   [(long)BATCH*CH*HW + 32];

// ---------------------------------------------------------------------------
// Conv1x1 GEMM (f32x2, at packed-fp32 roofline) — unchanged.
// ---------------------------------------------------------------------------
__global__ __launch_bounds__(256, 2)
void gemm_conv(const float* __restrict__ A,
               const float* __restrict__ B0,
               const float* __restrict__ B1,
               int K, int K0,
               float* __restrict__ C,
               const float* __restrict__ bias,
               float scale, int mode)
{
    const int tid = threadIdx.x;
    const int b   = blockIdx.z;
    const int n0  = blockIdx.x * 128;
    const int m0  = blockIdx.y * 128;
    const long boff = (long)b * CH * HW;
    const float* Bb0 = B0 + boff;
    const float* Bb1 = B1 ? (B1 + boff) : nullptr;
    float* Cb = C + boff;

    __shared__ float As[2][16][132];
    __shared__ float Bs[2][16][128];

    const int ty8 = (tid >> 4) * 8;
    const int tx8 = (tid & 15) * 8;
    const int arow0 = tid >> 2;
    const int acol  = (tid & 3) * 4;
    const int brow0 = tid >> 5;
    const int bcol  = (tid & 31) * 4;

    ull acc[8][4];
#pragma unroll
    for (int i = 0; i < 8; i++)
#pragma unroll
        for (int q = 0; q < 4; q++) acc[i][q] = 0ull;

    const int ntiles = K / 16;
    float4 ar[2], br[2];

#pragma unroll
    for (int p = 0; p < 2; p++)
        ar[p] = *(const float4*)&A[(long)(m0 + p * 64 + arow0) * K + acol];
#pragma unroll
    for (int p = 0; p < 2; p++) {
        int kr = p * 8 + brow0;
        const float* src = (kr < K0) ? (Bb0 + (long)kr * HW)
                                     : (Bb1 + (long)(kr - K0) * HW);
        br[p] = *(const float4*)&src[n0 + bcol];
    }
#pragma unroll
    for (int p = 0; p < 2; p++) {
        int row = p * 64 + arow0;
        As[0][acol + 0][row] = ar[p].x;
        As[0][acol + 1][row] = ar[p].y;
        As[0][acol + 2][row] = ar[p].z;
        As[0][acol + 3][row] = ar[p].w;
    }
#pragma unroll
    for (int p = 0; p < 2; p++)
        *(float4*)&Bs[0][p * 8 + brow0][bcol] = br[p];
    __syncthreads();

    for (int kt = 0; kt < ntiles; kt++) {
        const int cur = kt & 1, nxt = cur ^ 1;
        if (kt + 1 < ntiles) {
            int kb = (kt + 1) * 16;
#pragma unroll
            for (int p = 0; p < 2; p++)
                ar[p] = *(const float4*)&A[(long)(m0 + p * 64 + arow0) * K + kb + acol];
#pragma unroll
            for (int p = 0; p < 2; p++) {
                int kr = kb + p * 8 + brow0;
                const float* src = (kr < K0) ? (Bb0 + (long)kr * HW)
                                             : (Bb1 + (long)(kr - K0) * HW);
                br[p] = *(const float4*)&src[n0 + bcol];
            }
        }
#pragma unroll
        for (int kk = 0; kk < 16; kk++) {
            float4 a0 = *(const float4*)&As[cur][kk][ty8];
            float4 a1 = *(const float4*)&As[cur][kk][ty8 + 4];
            float4 b0 = *(const float4*)&Bs[cur][kk][tx8];
            float4 b1 = *(const float4*)&Bs[cur][kk][tx8 + 4];
            float a[8] = {a0.x,a0.y,a0.z,a0.w,a1.x,a1.y,a1.z,a1.w};
            ull b2[4] = {pack2(b0.x,b0.y), pack2(b0.z,b0.w),
                         pack2(b1.x,b1.y), pack2(b1.z,b1.w)};
#pragma unroll
            for (int i = 0; i < 8; i++) {
                ull ai = pack2b(a[i]);
#pragma unroll
                for (int q = 0; q < 4; q++) fma2(acc[i][q], ai, b2[q]);
            }
        }
        if (kt + 1 < ntiles) {
#pragma unroll
            for (int p = 0; p < 2; p++) {
                int row = p * 64 + arow0;
                As[nxt][acol + 0][row] = ar[p].x;
                As[nxt][acol + 1][row] = ar[p].y;
                As[nxt][acol + 2][row] = ar[p].z;
                As[nxt][acol + 3][row] = ar[p].w;
            }
#pragma unroll
            for (int p = 0; p < 2; p++)
                *(float4*)&Bs[nxt][p * 8 + brow0][bcol] = br[p];
            __syncthreads();
        }
    }

#pragma unroll
    for (int i = 0; i < 8; i++) {
        int o = m0 + ty8 + i;
        float bi = (mode == 0) ? bias[o] : 0.f;
        float c[8];
#pragma unroll
        for (int q = 0; q < 4; q++) unpack2(acc[i][q], c[2*q], c[2*q+1]);
#pragma unroll
        for (int j = 0; j < 8; j++) {
            if (mode == 0)      c[j] = fmaxf(c[j] + bi, 0.f);
            else if (mode == 1) c[j] = c[j] * scale;
        }
        float* dst = &Cb[(long)o * HW + n0 + tx8];
        *(float4*)&dst[0] = make_float4(c[0], c[1], c[2], c[3]);
        *(float4*)&dst[4] = make_float4(c[4], c[5], c[6], c[7]);
    }
}

// ---------------------------------------------------------------------------
// Halo attention v6: 512 threads / CTA, 1 CTA/SM, all loads up front,
// tf32 mma for QK^T and AV, staged coalesced output.
// smem (floats):
//   KW  @0      [208][68]  (rows 196..207 zero)  -> simT / OT overlay
//   QC  @14144  [64][72]
//   VC  @18752  [64][204]  (cols 196..203 zero)
//   REL @31808 (896), RED @32704 (8x64), MX @33216, INV @33280; TOT 33344
// ---------------------------------------------------------------------------
#define KW_OFF   0
#define KW_STR   68
#define QC_OFF   14144
#define QC_STR   72
#define VC_OFF   18752
#define VC_STR   204
#define ST_OFF   0
#define ST_STR   68
#define OT_OFF   0
#define OT_STR   72
#define REL_OFF  31808
#define RED_OFF  32704
#define MX_OFF   33216
#define INV_OFF  33280
#define SM_TOT   33344

__global__ __launch_bounds__(512, 1)
void attn_kernel(const float* __restrict__ gq, const float* __restrict__ gk,
                 const float* __restrict__ gv, const float* __restrict__ relh,
                 const float* __restrict__ relw, float* __restrict__ out)
{
    extern __shared__ float sm[];
    const int tid  = threadIdx.x;
    const int lane = tid & 31, w = tid >> 5;
    const int gid  = lane >> 2, tig = lane & 3;
    const int blk = blockIdx.x;
    const int h   = blockIdx.y;
    const int b   = blockIdx.z;
    const int by  = blk >> 4, bx = blk & 15;
    const int y0  = by * BLK, x0 = bx * BLK;
    const long base = ((long)b * CH + h * D) * HW;

    // ---- phase 0: rel tables + zero pads ------------------------------------
    for (int t = tid; t < 896; t += 512) {
        if (t < 448) sm[REL_OFF + t] = relh[t];
        else {
            int m = t - 448, jw = m >> 5, cc = m & 31;
            sm[REL_OFF + 448 + cc * 14 + jw] = relw[m];
        }
    }
    for (int t = tid; t < 12 * KW_STR; t += 512)
        sm[KW_OFF + 196 * KW_STR + t] = 0.f;
    {   // VC cols 196..203 zero
        int c = tid >> 3, q2 = tid & 7;
        sm[VC_OFF + c * VC_STR + 196 + q2] = 0.f;
    }
    __syncthreads();

    // ---- phase 1: load Q, K(+bias), V — all LDGs in flight together ---------
    {   // Q: one (c,row) per thread
        int c = tid >> 3, r = tid & 7;
        const float* src = gq + base + (long)c * HW + (y0 + r) * IMG + x0;
        float4 qa = *(const float4*)src;
        float4 qb = *(const float4*)(src + 4);
        qa.x=tf32r(qa.x); qa.y=tf32r(qa.y); qa.z=tf32r(qa.z); qa.w=tf32r(qa.w);
        qb.x=tf32r(qb.x); qb.y=tf32r(qb.y); qb.z=tf32r(qb.z); qb.w=tf32r(qb.w);
        *(float4*)&sm[QC_OFF + c * QC_STR + r * 8]     = qa;
        *(float4*)&sm[QC_OFF + c * QC_STR + r * 8 + 4] = qb;
    }
    for (int t = tid; t < 896; t += 512) {     // K window rows
        int c = t / 14, iw = t - c * 14;
        int y = y0 - HALO + iw;
        float wv[16];
        if ((unsigned)y < IMG) {
            const float* src = gk + base + (long)c * HW + y * IMG + x0 - 4;
            float4 f0 = *(const float4*)src;
            float4 f1 = *(const float4*)(src + 4);
            float4 f2 = *(const float4*)(src + 8);
            float4 f3 = *(const float4*)(src + 12);
            wv[0]=f0.x; wv[1]=f0.y; wv[2]=f0.z; wv[3]=f0.w;
            wv[4]=f1.x; wv[5]=f1.y; wv[6]=f1.z; wv[7]=f1.w;
            wv[8]=f2.x; wv[9]=f2.y; wv[10]=f2.z; wv[11]=f2.w;
            wv[12]=f3.x; wv[13]=f3.y; wv[14]=f3.z; wv[15]=f3.w;
            if (x0 == 0)   { wv[1]=0.f; wv[2]=0.f; wv[3]=0.f; }
            if (x0 == 120) { wv[12]=0.f; wv[13]=0.f; wv[14]=0.f; }
        } else {
#pragma unroll
            for (int m = 0; m < 16; m++) wv[m] = 0.f;
        }
        if (c < 32) {
            float bh = sm[REL_OFF + iw * 32 + c];
#pragma unroll
            for (int jw = 0; jw < 14; jw++)
                sm[KW_OFF + (iw * 14 + jw) * KW_STR + c] = tf32r(wv[jw + 1] + bh);
        } else {
            const float* rw = &sm[REL_OFF + 448 + (c - 32) * 14];
#pragma unroll
            for (int jw = 0; jw < 14; jw++)
                sm[KW_OFF + (iw * 14 + jw) * KW_STR + c] = tf32r(wv[jw + 1] + rw[jw]);
        }
    }
    for (int t = tid; t < 896; t += 512) {     // V window rows
        int c = t / 14, iw = t - c * 14;
        int y = y0 - HALO + iw;
        float wv[16];
        if ((unsigned)y < IMG) {
            const float* src = gv + base + (long)c * HW + y * IMG + x0 - 4;
            float4 f0 = *(const float4*)src;
            float4 f1 = *(const float4*)(src + 4);
            float4 f2 = *(const float4*)(src + 8);
            float4 f3 = *(const float4*)(src + 12);
            wv[0]=f0.x; wv[1]=f0.y; wv[2]=f0.z; wv[3]=f0.w;
            wv[4]=f1.x; wv[5]=f1.y; wv[6]=f1.z; wv[7]=f1.w;
            wv[8]=f2.x; wv[9]=f2.y; wv[10]=f2.z; wv[11]=f2.w;
            wv[12]=f3.x; wv[13]=f3.y; wv[14]=f3.z; wv[15]=f3.w;
            if (x0 == 0)   { wv[1]=0.f; wv[2]=0.f; wv[3]=0.f; }
            if (x0 == 120) { wv[12]=0.f; wv[13]=0.f; wv[14]=0.f; }
        } else {
#pragma unroll
            for (int m = 0; m < 16; m++) wv[m] = 0.f;
        }
        float* dst = &sm[VC_OFF + c * VC_STR + iw * 14];
#pragma unroll
        for (int jw = 0; jw < 14; jw++) dst[jw] = tf32r(wv[jw + 1]);
    }
    __syncthreads();

    // ---- phase 2: simT[208 x 64] = KW @ QC (16 warps: 13 m-tiles x 4 n-grp) --
    const int wm = w >> 2, wn = w & 3;
    const int mcnt  = (wm == 0) ? 4 : 3;
    const int mbase = ((wm == 0) ? 0 : (1 + 3 * wm)) * 16;
    float Cf[4][2][4];
#pragma unroll
    for (int mt = 0; mt < 4; mt++)
#pragma unroll
        for (int nt = 0; nt < 2; nt++)
#pragma unroll
            for (int q = 0; q < 4; q++) Cf[mt][nt][q] = 0.f;

#pragma unroll
    for (int ks = 0; ks < 8; ks++) {
        const int c0 = ks * 8;
        uint32_t Bf[2][2];
#pragma unroll
        for (int nt = 0; nt < 2; nt++) {
            int n = wn * 16 + nt * 8 + gid;
            Bf[nt][0] = __float_as_uint(sm[QC_OFF + (c0 + tig)     * QC_STR + n]);
            Bf[nt][1] = __float_as_uint(sm[QC_OFF + (c0 + tig + 4) * QC_STR + n]);
        }
#pragma unroll
        for (int mt = 0; mt < 4; mt++) {
            if (mt < mcnt) {
                int r = mbase + mt * 16 + gid;
                uint32_t a0 = __float_as_uint(sm[KW_OFF + r       * KW_STR + c0 + tig]);
                uint32_t a1 = __float_as_uint(sm[KW_OFF + (r + 8) * KW_STR + c0 + tig]);
                uint32_t a2 = __float_as_uint(sm[KW_OFF + r       * KW_STR + c0 + tig + 4]);
                uint32_t a3 = __float_as_uint(sm[KW_OFF + (r + 8) * KW_STR + c0 + tig + 4]);
                mma8(Cf[mt][0], a0, a1, a2, a3, Bf[0][0], Bf[0][1]);
                mma8(Cf[mt][1], a0, a1, a2, a3, Bf[1][0], Bf[1][1]);
            }
        }
    }
    __syncthreads();   // KW dead

#pragma unroll
    for (int mt = 0; mt < 4; mt++) {
        if (mt < mcnt) {
#pragma unroll
            for (int nt = 0; nt < 2; nt++) {
                int r = mbase + mt * 16 + gid;
                int cidx = wn * 16 + nt * 8 + 2 * tig;
                *(float2*)&sm[ST_OFF + r * ST_STR + cidx] =
                    make_float2(Cf[mt][nt][0], Cf[mt][nt][1]);
                *(float2*)&sm[ST_OFF + (r + 8) * ST_STR + cidx] =
                    make_float2(Cf[mt][nt][2], Cf[mt][nt][3]);
            }
        }
    }
    __syncthreads();

    // ---- phase 4: softmax over j per column i (8 j-groups) ------------------
    {
        const int i = tid & 63, p = tid >> 6;
        const int cnt = (p < 4) ? 25 : 24;
        const int jb  = (p < 4) ? p * 25 : 100 + (p - 4) * 24;
        float m = -1e30f;
        for (int jj = 0; jj < cnt; jj++)
            m = fmaxf(m, sm[ST_OFF + (jb + jj) * ST_STR + i]);
        sm[RED_OFF + p * 64 + i] = m;
        __syncthreads();
        if (tid < 64) {
            float mm = -1e30f;
#pragma unroll
            for (int pp = 0; pp < 8; pp++)
                mm = fmaxf(mm, sm[RED_OFF + pp * 64 + tid]);
            sm[MX_OFF + tid] = mm;
        }
        __syncthreads();
        float mm = sm[MX_OFF + i];
        float s = 0.f;
        for (int jj = 0; jj < cnt; jj++) {
            float e = __expf(sm[ST_OFF + (jb + jj) * ST_STR + i] - mm);
            s += e;
            sm[ST_OFF + (jb + jj) * ST_STR + i] = tf32r(e);
        }
        sm[RED_OFF + p * 64 + i] = s;
        if (tid < 4 * ST_STR) sm[ST_OFF + 196 * ST_STR + tid] = 0.f;  // AV k-pad
        __syncthreads();
        if (tid < 64) {
            float ss = 0.f;
#pragma unroll
            for (int pp = 0; pp < 8; pp++)
                ss += sm[RED_OFF + pp * 64 + tid];
            sm[INV_OFF + tid] = 1.f / ss;
        }
        __syncthreads();
    }

    // ---- phase 5: outT[64c x 64i] = VC @ simT (16 warps: 4x4 grid) ----------
    {
        const int c0 = (w >> 2) * 16;
        const int i0 = (w & 3) * 16;
        float Df[2][4];
#pragma unroll
        for (int nt = 0; nt < 2; nt++)
#pragma unroll
            for (int q = 0; q < 4; q++) Df[nt][q] = 0.f;

        for (int kt = 0; kt < 25; kt++) {
            const int j0 = kt * 8;
            const int cr = c0 + gid;
            uint32_t a0 = __float_as_uint(sm[VC_OFF + cr       * VC_STR + j0 + tig]);
            uint32_t a1 = __float_as_uint(sm[VC_OFF + (cr + 8) * VC_STR + j0 + tig]);
            uint32_t a2 = __float_as_uint(sm[VC_OFF + cr       * VC_STR + j0 + tig + 4]);
            uint32_t a3 = __float_as_uint(sm[VC_OFF + (cr + 8) * VC_STR + j0 + tig + 4]);
#pragma unroll
            for (int nt = 0; nt < 2; nt++) {
                int n = i0 + nt * 8 + gid;
                uint32_t b0 = __float_as_uint(sm[ST_OFF + (j0 + tig)     * ST_STR + n]);
                uint32_t b1 = __float_as_uint(sm[ST_OFF + (j0 + tig + 4) * ST_STR + n]);
                mma8(Df[nt], a0, a1, a2, a3, b0, b1);
            }
        }
        __syncthreads();   // simT dead; overlay OT

#pragma unroll
        for (int nt = 0; nt < 2; nt++) {
            int ii = i0 + nt * 8 + 2 * tig;
            float v0 = sm[INV_OFF + ii], v1 = sm[INV_OFF + ii + 1];
            int cr = c0 + gid;
            *(float2*)&sm[OT_OFF + cr * OT_STR + ii] =
                make_float2(Df[nt][0] * v0, Df[nt][1] * v1);
            *(float2*)&sm[OT_OFF + (cr + 8) * OT_STR + ii] =
                make_float2(Df[nt][2] * v0, Df[nt][3] * v1);
        }
        __syncthreads();

        // coalesced output: one (c,row) per thread, 2x STG.128
        int c = tid >> 3, r = tid & 7;
        float4 o0 = *(const float4*)&sm[OT_OFF + c * OT_STR + r * 8];
        float4 o1 = *(const float4*)&sm[OT_OFF + c * OT_STR + r * 8 + 4];
        float* dst = out + base + (long)c * HW + (y0 + r) * IMG + x0;
        *(float4*)&dst[0] = o0;
        *(float4*)&dst[4] = o1;
    }
}

// ---------------------------------------------------------------------------
extern "C" void kernel_launch(void* const* d_in, const int* in_sizes, int n_in,
                              void* d_out, int out_size)
{
    const float* noisy = (const float*)d_in[0];
    const float* aux   = (const float*)d_in[1];
    const float* w_map = (const float*)d_in[2];
    const float* b_map = (const float*)d_in[3];
    const float* w_q   = (const float*)d_in[4];
    const float* w_k   = (const float*)d_in[5];
    const float* w_v   = (const float*)d_in[6];
    const float* rel_h = (const float*)d_in[7];
    const float* rel_w = (const float*)d_in[8];
    float* out = (float*)d_out;

    float *naux, *q, *kraw, *vraw;
    cudaGetSymbolAddress((void**)&naux, g_naux);
    cudaGetSymbolAddress((void**)&q,    g_q);
    cudaGetSymbolAddress((void**)&kraw, g_k);
    cudaGetSymbolAddress((void**)&vraw, g_v);
    float* k = kraw + 16;
    float* v = vraw + 16;

    dim3 ggrid(HW / 128, CH / 128, BATCH);

    gemm_conv<<<ggrid, 256>>>(w_map, noisy, aux, 2 * CH, CH, naux, b_map, 1.f, 0);
    gemm_conv<<<ggrid, 256>>>(w_q, naux, nullptr, CH, CH, q, nullptr, 0.125f, 1);
    gemm_conv<<<ggrid, 256>>>(w_k, naux, nullptr, CH, CH, k, nullptr, 1.f, 2);
    gemm_conv<<<ggrid, 256>>>(w_v, noisy, nullptr, CH, CH, v, nullptr, 1.f, 2);

    size_t smem = (size_t)SM_TOT * sizeof(float);   // 133,376 B
    cudaFuncSetAttribute(attn_kernel,
                         cudaFuncAttributeMaxDynamicSharedMemorySize, (int)smem);
    attn_kernel<<<dim3(NB * NB, HEADS, BATCH), 512, smem>>>(q, k, v, rel_h, rel_w, out);
}